// round 3
// baseline (speedup 1.0000x reference)
#include <cuda_runtime.h>
#include <cuda_bf16.h>
#include <cstdint>

#define BB 8
#define QQ 100
#define TTD 50
#define HW 65536
#define SPLITS 64
#define HWB (HW / SPLITS)    // 1024
#define KC 64
#define NCHUNK (HWB / KC)    // 16
#define LDE 72               // smem row stride in bf16 elems (64 + 8 pad)
#define ROWB (LDE * 2)       // 144 bytes
#define SS_OFF (112 * ROWB)          // 16128
#define ST_OFF (2 * 112 * ROWB)      // 32256
#define STAGE_B (ST_OFF + 64 * ROWB) // 41472
#define DYN_SMEM (2 * STAGE_B)       // 82944

__device__ float g_DX[BB * 128 * 64];
__device__ float g_DS[BB * 128 * 64];
__device__ float g_SN[BB * 128];

__device__ __forceinline__ uint32_t smem_u32(const void* p) {
    return (uint32_t)__cvta_generic_to_shared(p);
}
__device__ __forceinline__ uint32_t pk(float a, float b) {
    __nv_bfloat162 h = __floats2bfloat162_rn(a, b);
    return *reinterpret_cast<uint32_t*>(&h);
}

__global__ __launch_bounds__(256, 2)
void cost_main_kernel(const float* __restrict__ pred, const int* __restrict__ tgt) {
    extern __shared__ __align__(16) char dyn[];
    const int tid  = threadIdx.x;
    const int warp = tid >> 5;
    const int lane = tid & 31;
    const int b    = blockIdx.x >> 6;
    const int split = blockIdx.x & 63;
    char* stg[2] = { dyn, dyn + STAGE_B };

    // ---- loader setup + prologue LDG issue (overlaps smem zero-init) ----
    const int r = tid >> 1, hf = tid & 1;
    const float4* px = nullptr;
    if (tid < 200)
        px = reinterpret_cast<const float4*>(
            pred + (size_t)(b * QQ + r) * HW + (size_t)split * HWB + hf * 32);
    const int4* pt = nullptr;
    uint32_t t_soff0 = 0;
    if (warp == 7) {
        pt = reinterpret_cast<const int4*>(
            tgt + (size_t)(b * TTD + (lane >> 4)) * HW + (size_t)split * HWB + (lane & 15) * 4);
        t_soff0 = (uint32_t)(ST_OFF + (lane >> 4) * ROWB + (lane & 15) * 8);
    }

    float4 xr[8];
    int4   trr[25];
    if (tid < 200) {
        #pragma unroll
        for (int j = 0; j < 8; j++) xr[j] = px[j];
    } else if (warp == 7) {
        #pragma unroll
        for (int k = 0; k < 25; k++) trr[k] = pt[k * (HW / 2)];
    }

    // ---- smem init: zero all, then ones rows (persist across chunks) ----
    for (int i = tid; i < DYN_SMEM / 16; i += 256)
        reinterpret_cast<uint4*>(dyn)[i] = make_uint4(0, 0, 0, 0);
    __syncthreads();
    if (tid < 32) {
        const uint32_t O = 0x3F803F80u;  // bf16 1.0 x2
        int s = tid >> 4, half = (tid >> 3) & 1, c = tid & 7;
        char* base = stg[s] + (half ? (ST_OFF + 50 * ROWB) : (SS_OFF + 100 * ROWB));
        reinterpret_cast<uint4*>(base)[c] = make_uint4(O, O, O, O);
    }

    // ---- mma setup ----
    float accX[8][4], accS[8][4];
    #pragma unroll
    for (int i = 0; i < 8; i++)
        #pragma unroll
        for (int j = 0; j < 4; j++) { accX[i][j] = 0.f; accS[i][j] = 0.f; }
    float accSP = 0.f;

    const int wm = (warp < 7) ? warp : 0;
    const uint32_t aoff = ((uint32_t)(wm * 16 + (lane & 15)) * LDE + ((lane >> 4) << 3)) * 2u;
    uint32_t boff[4];
    #pragma unroll
    for (int p = 0; p < 4; p++) {
        uint32_t row = (uint32_t)(p * 16 + (lane & 7) + (((lane >> 4) & 1) << 3));
        uint32_t col = ((lane >> 3) & 1) << 3;
        boff[p] = (uint32_t)ST_OFF + (row * LDE + col) * 2u;
    }

    for (int ch = 0; ch < NCHUNK; ch++) {
        char* sp = stg[ch & 1];

        // ---- convert prefetched regs -> smem[s] ----
        if (tid < 200) {
            char* wb = sp + r * ROWB + hf * 64;
            #pragma unroll
            for (int c = 0; c < 4; c++) {
                float4 v0 = xr[2 * c], v1 = xr[2 * c + 1];
                float xs[8] = { v0.x, v0.y, v0.z, v0.w, v1.x, v1.y, v1.z, v1.w };
                uint32_t wx[4], ws[4];
                #pragma unroll
                for (int j = 0; j < 4; j++) {
                    float x0 = xs[2 * j], x1 = xs[2 * j + 1];
                    float e0 = __expf(-fabsf(x0)), e1 = __expf(-fabsf(x1));
                    float i0 = __fdividef(1.f, 1.f + e0), i1 = __fdividef(1.f, 1.f + e1);
                    float s0 = (x0 >= 0.f) ? i0 : e0 * i0;
                    float s1 = (x1 >= 0.f) ? i1 : e1 * i1;
                    accSP += fmaxf(x0, 0.f) + __logf(1.f + e0)
                           + fmaxf(x1, 0.f) + __logf(1.f + e1);
                    wx[j] = pk(x0, x1);
                    ws[j] = pk(s0, s1);
                }
                *reinterpret_cast<uint4*>(wb + c * 16) =
                    make_uint4(wx[0], wx[1], wx[2], wx[3]);
                *reinterpret_cast<uint4*>(wb + SS_OFF + c * 16) =
                    make_uint4(ws[0], ws[1], ws[2], ws[3]);
            }
        } else if (warp == 7) {
            #pragma unroll
            for (int k = 0; k < 25; k++) {
                int4 v = trr[k];
                uint2 w = make_uint2(pk((float)v.x, (float)v.y), pk((float)v.z, (float)v.w));
                *reinterpret_cast<uint2*>(sp + t_soff0 + (uint32_t)(k * 2 * ROWB)) = w;
            }
        }
        __syncthreads();

        // ---- prefetch chunk ch+1 (latency hides behind mma below) ----
        if (ch + 1 < NCHUNK) {
            if (tid < 200) {
                #pragma unroll
                for (int j = 0; j < 8; j++) xr[j] = px[(ch + 1) * 16 + j];
            } else if (warp == 7) {
                #pragma unroll
                for (int k = 0; k < 25; k++) trr[k] = pt[k * (HW / 2) + (ch + 1) * 16];
            }
        }

        // ---- 112x64 double GEMM over KC=64 ----
        if (warp < 7) {
            const uint32_t sb = smem_u32(sp);
            const uint32_t xa = sb + aoff;
            const uint32_t sa = xa + SS_OFF;
            #pragma unroll
            for (int ks = 0; ks < 4; ks++) {
                uint32_t a0, a1, a2, a3, s0, s1, s2, s3;
                asm volatile("ldmatrix.sync.aligned.m8n8.x4.shared.b16 {%0,%1,%2,%3}, [%4];\n"
                    : "=r"(a0), "=r"(a1), "=r"(a2), "=r"(a3) : "r"(xa + ks * 32));
                asm volatile("ldmatrix.sync.aligned.m8n8.x4.shared.b16 {%0,%1,%2,%3}, [%4];\n"
                    : "=r"(s0), "=r"(s1), "=r"(s2), "=r"(s3) : "r"(sa + ks * 32));
                #pragma unroll
                for (int p = 0; p < 4; p++) {
                    uint32_t b0, b1, b2, b3;
                    asm volatile("ldmatrix.sync.aligned.m8n8.x4.shared.b16 {%0,%1,%2,%3}, [%4];\n"
                        : "=r"(b0), "=r"(b1), "=r"(b2), "=r"(b3) : "r"(sb + boff[p] + ks * 32));
                    asm volatile("mma.sync.aligned.m16n8k16.row.col.f32.bf16.bf16.f32 "
                        "{%0,%1,%2,%3},{%4,%5,%6,%7},{%8,%9},{%0,%1,%2,%3};\n"
                        : "+f"(accX[2*p][0]), "+f"(accX[2*p][1]), "+f"(accX[2*p][2]), "+f"(accX[2*p][3])
                        : "r"(a0), "r"(a1), "r"(a2), "r"(a3), "r"(b0), "r"(b1));
                    asm volatile("mma.sync.aligned.m16n8k16.row.col.f32.bf16.bf16.f32 "
                        "{%0,%1,%2,%3},{%4,%5,%6,%7},{%8,%9},{%0,%1,%2,%3};\n"
                        : "+f"(accX[2*p+1][0]), "+f"(accX[2*p+1][1]), "+f"(accX[2*p+1][2]), "+f"(accX[2*p+1][3])
                        : "r"(a0), "r"(a1), "r"(a2), "r"(a3), "r"(b2), "r"(b3));
                    asm volatile("mma.sync.aligned.m16n8k16.row.col.f32.bf16.bf16.f32 "
                        "{%0,%1,%2,%3},{%4,%5,%6,%7},{%8,%9},{%0,%1,%2,%3};\n"
                        : "+f"(accS[2*p][0]), "+f"(accS[2*p][1]), "+f"(accS[2*p][2]), "+f"(accS[2*p][3])
                        : "r"(s0), "r"(s1), "r"(s2), "r"(s3), "r"(b0), "r"(b1));
                    asm volatile("mma.sync.aligned.m16n8k16.row.col.f32.bf16.bf16.f32 "
                        "{%0,%1,%2,%3},{%4,%5,%6,%7},{%8,%9},{%0,%1,%2,%3};\n"
                        : "+f"(accS[2*p+1][0]), "+f"(accS[2*p+1][1]), "+f"(accS[2*p+1][2]), "+f"(accS[2*p+1][3])
                        : "r"(s0), "r"(s1), "r"(s2), "r"(s3), "r"(b2), "r"(b3));
                }
            }
        }
    }

    // ---- epilogue: predicated atomics into global scratch ----
    if (warp < 7) {
        const int mrow = warp * 16 + (lane >> 2);
        const int ncol = (lane & 3) * 2;
        float* dxb = g_DX + (size_t)b * 128 * 64;
        float* dsb = g_DS + (size_t)b * 128 * 64;
        #pragma unroll
        for (int nt = 0; nt < 8; nt++) {
            const int c  = nt * 8 + ncol;
            const int r0 = mrow, r1 = mrow + 8;
            if (r0 < QQ) {
                if (c     < TTD) atomicAdd(dxb + r0 * 64 + c,     accX[nt][0]);
                if (c + 1 < TTD) atomicAdd(dxb + r0 * 64 + c + 1, accX[nt][1]);
            }
            if (r1 < QQ) {
                if (c     < TTD) atomicAdd(dxb + r1 * 64 + c,     accX[nt][2]);
                if (c + 1 < TTD) atomicAdd(dxb + r1 * 64 + c + 1, accX[nt][3]);
            }
            if (r0 <= QQ) {
                if (c     <= TTD) atomicAdd(dsb + r0 * 64 + c,     accS[nt][0]);
                if (c + 1 <= TTD) atomicAdd(dsb + r0 * 64 + c + 1, accS[nt][1]);
            }
            if (r1 <= QQ) {
                if (c     <= TTD) atomicAdd(dsb + r1 * 64 + c,     accS[nt][2]);
                if (c + 1 <= TTD) atomicAdd(dsb + r1 * 64 + c + 1, accS[nt][3]);
            }
        }
    }

    // softplus row sums: pair-combine, one atomic per q-row
    float tot = accSP + __shfl_xor_sync(0xffffffffu, accSP, 1);
    if (tid < 200 && !(tid & 1))
        atomicAdd(&g_SN[b * 128 + r], tot);
}

__global__ void finalize_kernel(float* __restrict__ out) {
    int idx = blockIdx.x * blockDim.x + threadIdx.x;
    if (idx >= BB * QQ * TTD) return;
    int b   = idx / (QQ * TTD);
    int rem = idx % (QQ * TTD);
    int q   = rem / TTD;
    int t   = rem % TTD;

    const float dX   = g_DX[(b * 128 + q) * 64 + t];
    const float dS   = g_DS[(b * 128 + q) * 64 + t];
    const float sumS = g_DS[(b * 128 + q) * 64 + 50];
    const float sumT = g_DS[(b * 128 + 100) * 64 + t];
    const float sn   = g_SN[b * 128 + q];

    float ce   = (sn - dX) * (1.f / (float)HW);
    float dice = 1.f - (2.f * dS + 1.f) / (sumS + sumT + 1.f);
    out[idx] = ce + dice;
}

extern "C" void kernel_launch(void* const* d_in, const int* in_sizes, int n_in,
                              void* d_out, int out_size) {
    const float* pred = (const float*)d_in[0];
    const int*   tgt  = (const int*)d_in[1];
    float*       out  = (float*)d_out;

    cudaFuncSetAttribute(cost_main_kernel,
                         cudaFuncAttributeMaxDynamicSharedMemorySize, DYN_SMEM);

    void* p;
    cudaGetSymbolAddress(&p, g_DX); cudaMemsetAsync(p, 0, sizeof(float) * BB * 128 * 64);
    cudaGetSymbolAddress(&p, g_DS); cudaMemsetAsync(p, 0, sizeof(float) * BB * 128 * 64);
    cudaGetSymbolAddress(&p, g_SN); cudaMemsetAsync(p, 0, sizeof(float) * BB * 128);

    cost_main_kernel<<<BB * SPLITS, 256, DYN_SMEM>>>(pred, tgt);
    finalize_kernel<<<(BB * QQ * TTD + 255) / 256, 256>>>(out);
}

// round 4
// speedup vs baseline: 1.3752x; 1.3752x over previous
#include <cuda_runtime.h>
#include <cuda_bf16.h>
#include <cstdint>

#define BB 8
#define QQ 100
#define TTD 50
#define HW 65536
#define SPLITS 64
#define HWB (HW / SPLITS)    // 1024
#define KC 64
#define NCHUNK (HWB / KC)    // 16
#define LDE 72               // bf16 elems per smem row (64 + 8 pad)
#define ROWB 144             // bytes per row
#define MROWS 112
#define NROWS 56
#define S_OFF (MROWS * ROWB)             // 16128
#define T_OFF (2 * MROWS * ROWB)         // 32256
#define STAGE_B (T_OFF + NROWS * ROWB)   // 40320
#define RAW_OFF (2 * STAGE_B)            // 80640
#define RAW_B (TTD * KC * 4)             // 12800
#define DYN_SMEM (RAW_OFF + 2 * RAW_B)   // 106240

__device__ float g_DX[BB * 128 * 64];
__device__ float g_DS[BB * 128 * 64];
__device__ float g_SN[BB * 128];

__device__ __forceinline__ uint32_t smem_u32(const void* p) {
    return (uint32_t)__cvta_generic_to_shared(p);
}
__device__ __forceinline__ uint32_t pk(float a, float b) {
    __nv_bfloat162 h = __floats2bfloat162_rn(a, b);
    return *reinterpret_cast<uint32_t*>(&h);
}
__device__ __forceinline__ void cp16(uint32_t dst, const void* src) {
    asm volatile("cp.async.cg.shared.global [%0], [%1], 16;" :: "r"(dst), "l"(src));
}

__global__ __launch_bounds__(256, 2)
void cost_main_kernel(const float* __restrict__ pred, const int* __restrict__ tgt) {
    extern __shared__ __align__(16) char dyn[];
    const int tid  = threadIdx.x;
    const int warp = tid >> 5;
    const int lane = tid & 31;
    const int b    = blockIdx.x >> 6;
    const int split = blockIdx.x & 63;

    // ---- x loader setup + prologue LDG ----
    const int r = tid >> 1, hf = tid & 1;
    const bool isx = (tid < 200);
    const float4* px = nullptr;
    if (isx)
        px = reinterpret_cast<const float4*>(
            pred + (size_t)(b * QQ + r) * HW + (size_t)split * HWB + hf * 32);
    float4 xr[8];
    if (isx) {
        #pragma unroll
        for (int j = 0; j < 8; j++) xr[j] = px[j];
    }

    // ---- t prologue: cp.async chunk 0 into raw buf 0 ----
    const char* tbase = reinterpret_cast<const char*>(tgt)
                      + ((size_t)b * TTD * HW + (size_t)split * HWB) * 4;
    if (warp == 7) {
        #pragma unroll
        for (int i = 0; i < 25; i++) {
            int c = lane + 32 * i;
            int tr = c >> 4, cc = c & 15;
            cp16(smem_u32(dyn + RAW_OFF) + tr * 256 + cc * 16,
                 tbase + (size_t)tr * HW * 4 + cc * 16);
        }
        asm volatile("cp.async.commit_group;" ::: "memory");
    }

    // ---- init pad rows + ones rows in both stages ----
    for (int s = 0; s < 2; s++) {
        char* st = dyn + s * STAGE_B;
        // X rows 100..111 zero (1728B), S rows 101..111 zero (1584B)
        for (int i = tid; i < 108; i += 256)
            reinterpret_cast<uint4*>(st + 100 * ROWB)[i] = make_uint4(0, 0, 0, 0);
        for (int i = tid; i < 99; i += 256)
            reinterpret_cast<uint4*>(st + S_OFF + 101 * ROWB)[i] = make_uint4(0, 0, 0, 0);
        // T rows: row 50 pad + rows 51..55 zero (736B from T+50*144+128)
        for (int i = tid; i < 46; i += 256)
            reinterpret_cast<uint4*>(st + T_OFF + 50 * ROWB + 128)[i] = make_uint4(0, 0, 0, 0);
        // ones rows: S row 100 (data 128B) + its pad, T row 50 (data 128B)
        const uint32_t O = 0x3F803F80u;
        if (tid < 8) reinterpret_cast<uint4*>(st + S_OFF + 100 * ROWB)[tid] = make_uint4(O, O, O, O);
        else if (tid < 9) *reinterpret_cast<uint4*>(st + S_OFF + 100 * ROWB + 128) = make_uint4(0, 0, 0, 0);
        if (tid >= 16 && tid < 24)
            reinterpret_cast<uint4*>(st + T_OFF + 50 * ROWB)[tid - 16] = make_uint4(O, O, O, O);
    }
    __syncthreads();

    // ---- accumulators + mma addressing ----
    float accX[7][4], accS[7][4];
    #pragma unroll
    for (int i = 0; i < 7; i++)
        #pragma unroll
        for (int j = 0; j < 4; j++) { accX[i][j] = 0.f; accS[i][j] = 0.f; }
    float accSP = 0.f;

    const uint32_t aoff = (uint32_t)((warp & 7) % 7) * 16 * ROWB
                        + (uint32_t)(lane & 15) * ROWB + ((lane >> 4) << 4);
    uint32_t boff[3];
    #pragma unroll
    for (int p = 0; p < 3; p++) {
        uint32_t row = (uint32_t)(p * 16 + (lane & 7) + (((lane >> 4) & 1) << 3));
        boff[p] = (uint32_t)T_OFF + row * ROWB + (((lane >> 3) & 1) << 4);
    }
    const uint32_t boff6 = (uint32_t)T_OFF + (uint32_t)(48 + (lane & 7)) * ROWB
                         + (((lane >> 3) & 1) << 4);

    for (int ch = 0; ch < NCHUNK; ch++) {
        char* sp = dyn + (ch & 1) * STAGE_B;

        if (warp == 7) {
            // issue cp.async for ch+1 first (hidden behind conv+bar+mma)
            if (ch + 1 < NCHUNK) {
                char* rawn = dyn + RAW_OFF + ((ch + 1) & 1) * RAW_B;
                #pragma unroll
                for (int i = 0; i < 25; i++) {
                    int c = lane + 32 * i;
                    int tr = c >> 4, cc = c & 15;
                    cp16(smem_u32(rawn) + tr * 256 + cc * 16,
                         tbase + (size_t)tr * HW * 4 + ((ch + 1) * 64 + cc * 4) * 4);
                }
                asm volatile("cp.async.commit_group;" ::: "memory");
                asm volatile("cp.async.wait_group 1;" ::: "memory");
            } else {
                asm volatile("cp.async.wait_group 0;" ::: "memory");
            }
            // convert raw(ch) -> bf16 T tile(ch)
            char* raw = dyn + RAW_OFF + (ch & 1) * RAW_B;
            #pragma unroll
            for (int i = 0; i < 25; i++) {
                int c = lane + 32 * i;
                int tr = c >> 4, cc = c & 15;
                int4 v = *reinterpret_cast<int4*>(raw + tr * 256 + cc * 16);
                uint2 w = make_uint2((uint32_t)v.x * 0x3F80u + (uint32_t)v.y * 0x3F800000u,
                                     (uint32_t)v.z * 0x3F80u + (uint32_t)v.w * 0x3F800000u);
                *reinterpret_cast<uint2*>(sp + T_OFF + tr * ROWB + cc * 8) = w;
            }
        } else if (isx) {
            // convert prefetched x -> X/S tiles(ch)
            char* wb = sp + r * ROWB + hf * 64;
            #pragma unroll
            for (int c = 0; c < 4; c++) {
                float4 v0 = xr[2 * c], v1 = xr[2 * c + 1];
                float xs[8] = { v0.x, v0.y, v0.z, v0.w, v1.x, v1.y, v1.z, v1.w };
                uint32_t wx[4], ws[4];
                #pragma unroll
                for (int j = 0; j < 4; j++) {
                    float x0 = xs[2 * j], x1 = xs[2 * j + 1];
                    float e0 = __expf(-fabsf(x0)), e1 = __expf(-fabsf(x1));
                    float i0 = __fdividef(1.f, 1.f + e0), i1 = __fdividef(1.f, 1.f + e1);
                    float s0 = (x0 >= 0.f) ? i0 : e0 * i0;
                    float s1 = (x1 >= 0.f) ? i1 : e1 * i1;
                    accSP += fmaxf(x0, 0.f) + __logf(1.f + e0)
                           + fmaxf(x1, 0.f) + __logf(1.f + e1);
                    wx[j] = pk(x0, x1);
                    ws[j] = pk(s0, s1);
                }
                *reinterpret_cast<uint4*>(wb + c * 16) = make_uint4(wx[0], wx[1], wx[2], wx[3]);
                *reinterpret_cast<uint4*>(wb + S_OFF + c * 16) = make_uint4(ws[0], ws[1], ws[2], ws[3]);
            }
            // prefetch x for ch+1 (in flight across bar + mma)
            if (ch + 1 < NCHUNK) {
                #pragma unroll
                for (int j = 0; j < 8; j++) xr[j] = px[(ch + 1) * 16 + j];
            }
        }
        __syncthreads();

        // ---- 112x56 double GEMM over KC=64 (warps 0-6) ----
        if (warp < 7) {
            const uint32_t sb = smem_u32(sp);
            const uint32_t xa = sb + aoff;
            const uint32_t sa = xa + S_OFF;
            #pragma unroll
            for (int ks = 0; ks < 4; ks++) {
                uint32_t a0, a1, a2, a3, s0, s1, s2, s3;
                asm volatile("ldmatrix.sync.aligned.m8n8.x4.shared.b16 {%0,%1,%2,%3}, [%4];\n"
                    : "=r"(a0), "=r"(a1), "=r"(a2), "=r"(a3) : "r"(xa + ks * 32));
                asm volatile("ldmatrix.sync.aligned.m8n8.x4.shared.b16 {%0,%1,%2,%3}, [%4];\n"
                    : "=r"(s0), "=r"(s1), "=r"(s2), "=r"(s3) : "r"(sa + ks * 32));
                #pragma unroll
                for (int p = 0; p < 3; p++) {
                    uint32_t b0, b1, b2, b3;
                    asm volatile("ldmatrix.sync.aligned.m8n8.x4.shared.b16 {%0,%1,%2,%3}, [%4];\n"
                        : "=r"(b0), "=r"(b1), "=r"(b2), "=r"(b3) : "r"(sb + boff[p] + ks * 32));
                    asm volatile("mma.sync.aligned.m16n8k16.row.col.f32.bf16.bf16.f32 "
                        "{%0,%1,%2,%3},{%4,%5,%6,%7},{%8,%9},{%0,%1,%2,%3};\n"
                        : "+f"(accX[2*p][0]), "+f"(accX[2*p][1]), "+f"(accX[2*p][2]), "+f"(accX[2*p][3])
                        : "r"(a0), "r"(a1), "r"(a2), "r"(a3), "r"(b0), "r"(b1));
                    asm volatile("mma.sync.aligned.m16n8k16.row.col.f32.bf16.bf16.f32 "
                        "{%0,%1,%2,%3},{%4,%5,%6,%7},{%8,%9},{%0,%1,%2,%3};\n"
                        : "+f"(accX[2*p+1][0]), "+f"(accX[2*p+1][1]), "+f"(accX[2*p+1][2]), "+f"(accX[2*p+1][3])
                        : "r"(a0), "r"(a1), "r"(a2), "r"(a3), "r"(b2), "r"(b3));
                    asm volatile("mma.sync.aligned.m16n8k16.row.col.f32.bf16.bf16.f32 "
                        "{%0,%1,%2,%3},{%4,%5,%6,%7},{%8,%9},{%0,%1,%2,%3};\n"
                        : "+f"(accS[2*p][0]), "+f"(accS[2*p][1]), "+f"(accS[2*p][2]), "+f"(accS[2*p][3])
                        : "r"(s0), "r"(s1), "r"(s2), "r"(s3), "r"(b0), "r"(b1));
                    asm volatile("mma.sync.aligned.m16n8k16.row.col.f32.bf16.bf16.f32 "
                        "{%0,%1,%2,%3},{%4,%5,%6,%7},{%8,%9},{%0,%1,%2,%3};\n"
                        : "+f"(accS[2*p+1][0]), "+f"(accS[2*p+1][1]), "+f"(accS[2*p+1][2]), "+f"(accS[2*p+1][3])
                        : "r"(s0), "r"(s1), "r"(s2), "r"(s3), "r"(b2), "r"(b3));
                }
                {   // n-tile 6 via x2
                    uint32_t b0, b1;
                    asm volatile("ldmatrix.sync.aligned.m8n8.x2.shared.b16 {%0,%1}, [%2];\n"
                        : "=r"(b0), "=r"(b1) : "r"(sb + boff6 + ks * 32));
                    asm volatile("mma.sync.aligned.m16n8k16.row.col.f32.bf16.bf16.f32 "
                        "{%0,%1,%2,%3},{%4,%5,%6,%7},{%8,%9},{%0,%1,%2,%3};\n"
                        : "+f"(accX[6][0]), "+f"(accX[6][1]), "+f"(accX[6][2]), "+f"(accX[6][3])
                        : "r"(a0), "r"(a1), "r"(a2), "r"(a3), "r"(b0), "r"(b1));
                    asm volatile("mma.sync.aligned.m16n8k16.row.col.f32.bf16.bf16.f32 "
                        "{%0,%1,%2,%3},{%4,%5,%6,%7},{%8,%9},{%0,%1,%2,%3};\n"
                        : "+f"(accS[6][0]), "+f"(accS[6][1]), "+f"(accS[6][2]), "+f"(accS[6][3])
                        : "r"(s0), "r"(s1), "r"(s2), "r"(s3), "r"(b0), "r"(b1));
                }
            }
        }
    }

    // ---- epilogue: predicated atomics ----
    if (warp < 7) {
        const int mrow = warp * 16 + (lane >> 2);
        const int ncol = (lane & 3) * 2;
        float* dxb = g_DX + (size_t)b * 128 * 64;
        float* dsb = g_DS + (size_t)b * 128 * 64;
        #pragma unroll
        for (int nt = 0; nt < 7; nt++) {
            const int c  = nt * 8 + ncol;
            const int r0 = mrow, r1 = mrow + 8;
            if (r0 < QQ) {
                if (c     < TTD) atomicAdd(dxb + r0 * 64 + c,     accX[nt][0]);
                if (c + 1 < TTD) atomicAdd(dxb + r0 * 64 + c + 1, accX[nt][1]);
            }
            if (r1 < QQ) {
                if (c     < TTD) atomicAdd(dxb + r1 * 64 + c,     accX[nt][2]);
                if (c + 1 < TTD) atomicAdd(dxb + r1 * 64 + c + 1, accX[nt][3]);
            }
            if (r0 <= QQ) {
                if (c     <= TTD) atomicAdd(dsb + r0 * 64 + c,     accS[nt][0]);
                if (c + 1 <= TTD) atomicAdd(dsb + r0 * 64 + c + 1, accS[nt][1]);
            }
            if (r1 <= QQ) {
                if (c     <= TTD) atomicAdd(dsb + r1 * 64 + c,     accS[nt][2]);
                if (c + 1 <= TTD) atomicAdd(dsb + r1 * 64 + c + 1, accS[nt][3]);
            }
        }
    }

    float tot = accSP + __shfl_xor_sync(0xffffffffu, accSP, 1);
    if (isx && !(tid & 1))
        atomicAdd(&g_SN[b * 128 + r], tot);
}

__global__ void zero_kernel() {
    int idx = blockIdx.x * blockDim.x + threadIdx.x;
    const int n4 = (2 * BB * 128 * 64 + BB * 128) / 4;  // 33056 uint4
    float4 z = make_float4(0.f, 0.f, 0.f, 0.f);
    if (idx < BB * 128 * 64 / 4) reinterpret_cast<float4*>(g_DX)[idx] = z;
    int i2 = idx - BB * 128 * 64 / 4;
    if (i2 >= 0 && i2 < BB * 128 * 64 / 4) reinterpret_cast<float4*>(g_DS)[i2] = z;
    int i3 = idx - 2 * (BB * 128 * 64 / 4);
    if (i3 >= 0 && i3 < BB * 128 / 4) reinterpret_cast<float4*>(g_SN)[i3] = z;
    (void)n4;
}

__global__ void finalize_kernel(float* __restrict__ out) {
    int idx = blockIdx.x * blockDim.x + threadIdx.x;
    if (idx >= BB * QQ * TTD) return;
    int b   = idx / (QQ * TTD);
    int rem = idx % (QQ * TTD);
    int q   = rem / TTD;
    int t   = rem % TTD;

    const float dX   = g_DX[(b * 128 + q) * 64 + t];
    const float dS   = g_DS[(b * 128 + q) * 64 + t];
    const float sumS = g_DS[(b * 128 + q) * 64 + 50];
    const float sumT = g_DS[(b * 128 + 100) * 64 + t];
    const float sn   = g_SN[b * 128 + q];

    float ce   = (sn - dX) * (1.f / (float)HW);
    float dice = 1.f - (2.f * dS + 1.f) / (sumS + sumT + 1.f);
    out[idx] = ce + dice;
}

__global__ void dummy_kernel() {}

extern "C" void kernel_launch(void* const* d_in, const int* in_sizes, int n_in,
                              void* d_out, int out_size) {
    const float* pred = (const float*)d_in[0];
    const int*   tgt  = (const int*)d_in[1];
    float*       out  = (float*)d_out;

    cudaFuncSetAttribute(cost_main_kernel,
                         cudaFuncAttributeMaxDynamicSharedMemorySize, DYN_SMEM);

    // 4 kernel launches/iter so ncu (-s 5) lands on cost_main_kernel (5 mod 4 == 1)
    zero_kernel<<<(2 * BB * 128 * 64 / 4 + BB * 128 / 4 + 255) / 256, 256>>>();
    cost_main_kernel<<<BB * SPLITS, 256, DYN_SMEM>>>(pred, tgt);
    finalize_kernel<<<(BB * QQ * TTD + 255) / 256, 256>>>(out);
    dummy_kernel<<<1, 32>>>();
}